// round 16
// baseline (speedup 1.0000x reference)
#include <cuda_runtime.h>
#include <math.h>
#include <stdint.h>

#define CL 32
#define NOBJ 32
#define PADW 68   // ct row stride (floats) — conflict-free scalar loads

struct Params {
  const float *s;
  const float *enc_w, *enc_b;
  const float *self_w0, *self_b0, *self_w1, *self_b1;
  const float *rel_w0, *rel_b0, *rel_w1, *rel_b1, *rel_w2, *rel_b2;
  const float *att_w0, *att_b0, *att_w1, *att_b1, *att_w2, *att_b2;
  const float *aff_w0, *aff_b0, *aff_w1, *aff_b1, *aff_w2, *aff_b2;
  const float *out_w0, *out_b0, *out_w1, *out_b1;
  float *out;
};

__device__ __forceinline__ uint32_t tf32_rna(float x) {
  uint32_t r;
  asm("cvt.rna.tf32.f32 %0, %1;" : "=r"(r) : "f"(x));
  return r;
}

// m16n8k8 tf32 MMA: D = A@B + D. A row-major, B col-major. 32-bit operands only.
#define MMA_TF32(c0, c1, c2, c3, a0, a1, a2, a3, b0, b1)                       \
  asm("mma.sync.aligned.m16n8k8.row.col.f32.tf32.tf32.f32 "                    \
      "{%0,%1,%2,%3}, {%4,%5,%6,%7}, {%8,%9}, {%0,%1,%2,%3};"                  \
      : "+f"(c0), "+f"(c1), "+f"(c2), "+f"(c3)                                 \
      : "r"(a0), "r"(a1), "r"(a2), "r"(a3), "r"(b0), "r"(b1))

#define FOR_NT(F) F(0) F(1) F(2) F(3)

__global__ void __launch_bounds__(256, 2) dynamics_kernel(Params p)
{
  // ---- shared (~45.6 KB) ----
  __shared__ __align__(16) float s2[NOBJ * CL];            // 4 KB
  __shared__ __align__(16) float paF[NOBJ * 64];           // 8 KB frag-order (k0,k0+4) pairs; tail t1/t2
  __shared__ __align__(16) float ctT[33 * PADW];           // 8.98 KB
  __shared__ __align__(16) uint4 Wf[8 * 4 * 32];           // 16 KB: per-lane {bh0,bh1,bl0,bl1}; sdyn/t3 alias
  __shared__ __align__(16) float wdF[64];                  // frag-order dist-weight row
  __shared__ __align__(16) float ssm[NOBJ * CL];           // 4 KB: S matrix
  __shared__ __align__(16) float attv[NOBJ * CL];          // 4 KB: ssrc / att / h1
  __shared__ __align__(16) float miscA[32], miscB[32], miscC[32], avec[32];
  __shared__ float bA2s;

  float* sdyn = reinterpret_cast<float*>(Wf);              // first 1024 floats
  float* t3s  = reinterpret_cast<float*>(Wf) + 1024;       // next 1024 floats

  const int n    = blockIdx.x;
  const int t    = threadIdx.x;
  const int lane = t & 31;
  const int w    = t >> 5;
  const int gid  = lane >> 2;   // groupID
  const int tig  = lane & 3;    // threadID in group

  // ---- stage raw s (overlay in attv) ----
  {
    float* ssrc = attv;
    const float* sp = p.s + (size_t)n * (NOBJ * 16);
    for (int idx = t; idx < NOBJ * 16; idx += 256) ssrc[idx] = sp[idx];
  }
  __syncthreads();

  // ---- s2 = concat(s[:, :2], (s @ enc_w + enc_b)[:, 2:]) ----
  {
    const float* ssrc = attv;
    for (int idx = t; idx < NOBJ * CL; idx += 256) {
      int i = idx >> 5, c = idx & 31;
      float acc = __ldg(&p.enc_b[c]);
      #pragma unroll
      for (int k = 0; k < 16; ++k)
        acc = fmaf(ssrc[i * 16 + k], __ldg(&p.enc_w[k * 32 + c]), acc);
      s2[idx] = (c < 2) ? ssrc[i * 16 + c] : acc;
    }
  }
  __syncthreads();

  // ================= PAIR PHASE (tensor cores, tf32 x2) =================
  #pragma unroll 1
  for (int br = 0; br < 2; ++br) {
    const float* W0  = br ? p.rel_w0 : p.att_w0;
    const float* B0  = br ? p.rel_b0 : p.att_b0;
    const float* W1  = br ? p.rel_w1 : p.att_w1;
    const float* B1s = br ? p.rel_b1 : p.att_b1;

    // ---- stage W1 hi/lo into fragment-order uint4 smem ----
    for (int e = t; e < 2048; e += 256) {
      int k = e >> 5, nn = e & 31;
      float wv = __ldg(&W1[e]);                 // W1[k*32+nn], coalesced
      uint32_t hi = tf32_rna(wv);
      uint32_t lo = tf32_rna(wv - __uint_as_float(hi));
      int kt = k >> 3, kin = k & 7;
      int tg = kin & 3, slot = kin >> 2;        // slot 0 -> b0, 1 -> b1
      int nt = nn >> 3, gd = nn & 7;
      uint32_t* dst = reinterpret_cast<uint32_t*>(
          &Wf[(kt * 4 + nt) * 32 + (gd * 4 + tg)]);
      dst[slot]     = hi;                        // .x/.y
      dst[slot + 2] = lo;                        // .z/.w
    }
    if (t < 64) {
      int k = t, kt = k >> 3, kin = k & 7;
      wdF[(kt * 4 + (kin & 3)) * 2 + (kin >> 2)] = __ldg(&W0[64 * 64 + k]);
    } else if (t < 96) {
      int c = t - 64;
      miscA[c] = __ldg(&B1s[c]);
      if (!br) miscB[c] = __ldg(&p.att_w2[c]);
      else     miscC[c] = __ldg(&p.rel_b2[c]);
    } else if (t == 96 && !br) {
      bA2s = __ldg(&p.att_b2[0]);
    }

    // ---- projections: paF (bias folded, frag order) and ctT (padded) ----
    for (int idx = t; idx < 1024; idx += 256) {
      int io = idx >> 5, k = (idx & 31) * 2;    // k even: k,k+1 same slot
      float a0 = 0.f, a1 = 0.f, c0 = 0.f, c1 = 0.f;
      #pragma unroll
      for (int cc = 0; cc < 32; ++cc) {
        float sv = s2[io * 32 + cc];
        float2 wa = __ldg(reinterpret_cast<const float2*>(&W0[cc * 64 + k]));
        float2 wc = __ldg(reinterpret_cast<const float2*>(&W0[(32 + cc) * 64 + k]));
        a0 = fmaf(sv, wa.x, a0);
        a1 = fmaf(sv, wa.y, a1);
        c0 = fmaf(sv, wc.x, c0);
        c1 = fmaf(sv, wc.y, c1);
      }
      float2 bv = __ldg(reinterpret_cast<const float2*>(&B0[k]));
      int kt = k >> 3, kin = k & 7, slot = kin >> 2;
      int base = io * 64 + (kt * 4 + (kin & 3)) * 2 + slot;
      paF[base]     = a0 + bv.x;                 // k   -> (tig=kin&3, slot)
      paF[base + 2] = a1 + bv.y;                 // k+1 -> (tig+1, same slot)
      ctT[io * PADW + k]     = c0;
      ctT[io * PADW + k + 1] = c1;
    }
    __syncthreads();

    #pragma unroll 1
    for (int q = 0; q < 4; ++q) {
      const int i = w * 4 + q;
      const int jA = gid, jB = gid + 8, jC = gid + 16, jD = gid + 24;
      const int jA68 = jA * PADW, jB68 = jB * PADW;
      const int jC68 = jC * PADW, jD68 = jD * PADW;
      const float2* paf2 = reinterpret_cast<const float2*>(paF + i * 64);
      const float2* wdf2 = reinterpret_cast<const float2*>(wdF);

      float pix = s2[i * 32 + 0], piy = s2[i * 32 + 1];
      float dxA = pix - s2[jA * 32 + 0], dyA = piy - s2[jA * 32 + 1];
      float dxB = pix - s2[jB * 32 + 0], dyB = piy - s2[jB * 32 + 1];
      float dxC = pix - s2[jC * 32 + 0], dyC = piy - s2[jC * 32 + 1];
      float dxD = pix - s2[jD * 32 + 0], dyD = piy - s2[jD * 32 + 1];
      float dA = fmaf(dxA, dxA, dyA * dyA);
      float dB = fmaf(dxB, dxB, dyB * dyB);
      float dC = fmaf(dxC, dxC, dyC * dyC);
      float dD = fmaf(dxD, dxD, dyD * dyD);

      float bb0a = miscA[0  + 2 * tig], bb0b = miscA[0  + 2 * tig + 1];
      float bb1a = miscA[8  + 2 * tig], bb1b = miscA[8  + 2 * tig + 1];
      float bb2a = miscA[16 + 2 * tig], bb2b = miscA[16 + 2 * tig + 1];
      float bb3a = miscA[24 + 2 * tig], bb3b = miscA[24 + 2 * tig + 1];

#define DECL_C(nt)                                                             \
      float c0n##nt##_0 = bb##nt##a, c0n##nt##_1 = bb##nt##b,                  \
            c0n##nt##_2 = bb##nt##a, c0n##nt##_3 = bb##nt##b,                  \
            c1n##nt##_0 = bb##nt##a, c1n##nt##_1 = bb##nt##b,                  \
            c1n##nt##_2 = bb##nt##a, c1n##nt##_3 = bb##nt##b;
      FOR_NT(DECL_C)
#undef DECL_C

      #pragma unroll 1
      for (int kt = 0; kt < 8; ++kt) {
        const int k0 = kt * 8 + tig;
        const int k1 = k0 + 4;
        const int fi = kt * 4 + tig;

        float2 paf = paf2[fi];                   // (pa[k0], pa[k1])
        float2 wkf = wdf2[fi];                   // (wd[k0], wd[k1])

        float vA0 = fmaxf(fmaf(dA, wkf.x, paf.x + ctT[jA68 + k0]), 0.f);
        float vB0 = fmaxf(fmaf(dB, wkf.x, paf.x + ctT[jB68 + k0]), 0.f);
        float vC0 = fmaxf(fmaf(dC, wkf.x, paf.x + ctT[jC68 + k0]), 0.f);
        float vD0 = fmaxf(fmaf(dD, wkf.x, paf.x + ctT[jD68 + k0]), 0.f);
        float vA1 = fmaxf(fmaf(dA, wkf.y, paf.y + ctT[jA68 + k1]), 0.f);
        float vB1 = fmaxf(fmaf(dB, wkf.y, paf.y + ctT[jB68 + k1]), 0.f);
        float vC1 = fmaxf(fmaf(dC, wkf.y, paf.y + ctT[jC68 + k1]), 0.f);
        float vD1 = fmaxf(fmaf(dD, wkf.y, paf.y + ctT[jD68 + k1]), 0.f);

        uint32_t hA0 = tf32_rna(vA0), hB0 = tf32_rna(vB0);
        uint32_t hC0 = tf32_rna(vC0), hD0 = tf32_rna(vD0);
        uint32_t hA1 = tf32_rna(vA1), hB1 = tf32_rna(vB1);
        uint32_t hC1 = tf32_rna(vC1), hD1 = tf32_rna(vD1);

#define MMA_NT(nt) {                                                           \
        uint4 wv = Wf[(kt * 4 + nt) * 32 + lane];                              \
        MMA_TF32(c0n##nt##_0, c0n##nt##_1, c0n##nt##_2, c0n##nt##_3,           \
                 hA0, hB0, hA1, hB1, wv.x, wv.y);                              \
        MMA_TF32(c0n##nt##_0, c0n##nt##_1, c0n##nt##_2, c0n##nt##_3,           \
                 hA0, hB0, hA1, hB1, wv.z, wv.w);                              \
        MMA_TF32(c1n##nt##_0, c1n##nt##_1, c1n##nt##_2, c1n##nt##_3,           \
                 hC0, hD0, hC1, hD1, wv.x, wv.y);                              \
        MMA_TF32(c1n##nt##_0, c1n##nt##_1, c1n##nt##_2, c1n##nt##_3,           \
                 hC0, hD0, hC1, hD1, wv.z, wv.w); }
        FOR_NT(MMA_NT)
#undef MMA_NT
      }

      if (!br) {
        // ---- att epilogue: logit = b2 + sum_n relu(C)*w2[n] ----
        float lgA = 0.f, lgB = 0.f, lgC = 0.f, lgD = 0.f;
#define ATT_NT(nt) {                                                           \
        float w2a = miscB[nt * 8 + 2 * tig], w2b = miscB[nt * 8 + 2 * tig + 1];\
        lgA = fmaf(fmaxf(c0n##nt##_0, 0.f), w2a, lgA);                         \
        lgA = fmaf(fmaxf(c0n##nt##_1, 0.f), w2b, lgA);                         \
        lgB = fmaf(fmaxf(c0n##nt##_2, 0.f), w2a, lgB);                         \
        lgB = fmaf(fmaxf(c0n##nt##_3, 0.f), w2b, lgB);                         \
        lgC = fmaf(fmaxf(c1n##nt##_0, 0.f), w2a, lgC);                         \
        lgC = fmaf(fmaxf(c1n##nt##_1, 0.f), w2b, lgC);                         \
        lgD = fmaf(fmaxf(c1n##nt##_2, 0.f), w2a, lgD);                         \
        lgD = fmaf(fmaxf(c1n##nt##_3, 0.f), w2b, lgD); }
        FOR_NT(ATT_NT)
#undef ATT_NT
        lgA += __shfl_xor_sync(0xffffffffu, lgA, 1);
        lgA += __shfl_xor_sync(0xffffffffu, lgA, 2);
        lgB += __shfl_xor_sync(0xffffffffu, lgB, 1);
        lgB += __shfl_xor_sync(0xffffffffu, lgB, 2);
        lgC += __shfl_xor_sync(0xffffffffu, lgC, 1);
        lgC += __shfl_xor_sync(0xffffffffu, lgC, 2);
        lgD += __shfl_xor_sync(0xffffffffu, lgD, 1);
        lgD += __shfl_xor_sync(0xffffffffu, lgD, 2);
        float aA = (jA == i) ? 0.f : expf(bA2s + lgA);
        float aB = (jB == i) ? 0.f : expf(bA2s + lgB);
        float aC = (jC == i) ? 0.f : expf(bA2s + lgC);
        float aD = (jD == i) ? 0.f : expf(bA2s + lgD);
        if (tig == 0) {
          attv[i * 32 + jA] = aA;
          attv[i * 32 + jB] = aB;
          attv[i * 32 + jC] = aC;
          attv[i * 32 + jD] = aD;
        }
      } else {
        // ---- rel epilogue: S[i,col] = sum_j att*relu(C); A[i] = sum_j att ----
        float atA = attv[i * 32 + jA];
        float atB = attv[i * 32 + jB];
        float atC = attv[i * 32 + jC];
        float atD = attv[i * 32 + jD];
#define REL_NT(nt)                                                             \
        float ps##nt##a = fmaf(atA, fmaxf(c0n##nt##_0, 0.f),                   \
                          fmaf(atB, fmaxf(c0n##nt##_2, 0.f),                   \
                          fmaf(atC, fmaxf(c1n##nt##_0, 0.f),                   \
                               atD * fmaxf(c1n##nt##_2, 0.f))));               \
        float ps##nt##b = fmaf(atA, fmaxf(c0n##nt##_1, 0.f),                   \
                          fmaf(atB, fmaxf(c0n##nt##_3, 0.f),                   \
                          fmaf(atC, fmaxf(c1n##nt##_1, 0.f),                   \
                               atD * fmaxf(c1n##nt##_3, 0.f))));
        FOR_NT(REL_NT)
#undef REL_NT
#define RED_NT(nt) {                                                           \
        ps##nt##a += __shfl_xor_sync(0xffffffffu, ps##nt##a, 4);               \
        ps##nt##a += __shfl_xor_sync(0xffffffffu, ps##nt##a, 8);               \
        ps##nt##a += __shfl_xor_sync(0xffffffffu, ps##nt##a, 16);              \
        ps##nt##b += __shfl_xor_sync(0xffffffffu, ps##nt##b, 4);               \
        ps##nt##b += __shfl_xor_sync(0xffffffffu, ps##nt##b, 8);               \
        ps##nt##b += __shfl_xor_sync(0xffffffffu, ps##nt##b, 16); }
        FOR_NT(RED_NT)
#undef RED_NT
        if (gid == 0) {
#define ST_NT(nt) {                                                            \
          ssm[i * 32 + nt * 8 + 2 * tig]     = ps##nt##a;                      \
          ssm[i * 32 + nt * 8 + 2 * tig + 1] = ps##nt##b; }
          FOR_NT(ST_NT)
#undef ST_NT
        }
        float asum = atA + atB + atC + atD;
        asum += __shfl_xor_sync(0xffffffffu, asum, 4);
        asum += __shfl_xor_sync(0xffffffffu, asum, 8);
        asum += __shfl_xor_sync(0xffffffffu, asum, 16);
        if (lane == 0) avec[i] = asum;
      }
    }
    __syncthreads();
  }

  // ---- self branch (after pair; h1 in attv, out to sdyn alias) ----
  for (int idx = t; idx < 512; idx += 256) {
    int i = idx >> 4, c = (idx & 15) * 2;
    float2 b = __ldg(reinterpret_cast<const float2*>(&p.self_b0[c]));
    float acc0 = b.x, acc1 = b.y;
    #pragma unroll
    for (int k = 0; k < 32; ++k) {
      float x = s2[i * 32 + k];
      float2 wv = __ldg(reinterpret_cast<const float2*>(&p.self_w0[k * 32 + c]));
      acc0 = fmaf(x, wv.x, acc0);
      acc1 = fmaf(x, wv.y, acc1);
    }
    attv[i * 32 + c]     = fmaxf(acc0, 0.0f);
    attv[i * 32 + c + 1] = fmaxf(acc1, 0.0f);
  }
  __syncthreads();
  for (int idx = t; idx < 512; idx += 256) {
    int i = idx >> 4, c = (idx & 15) * 2;
    float2 b = __ldg(reinterpret_cast<const float2*>(&p.self_b1[c]));
    float acc0 = b.x + attv[i * 32 + c];
    float acc1 = b.y + attv[i * 32 + c + 1];
    #pragma unroll
    for (int k = 0; k < 32; ++k) {
      float x = attv[i * 32 + k];
      float2 wv = __ldg(reinterpret_cast<const float2*>(&p.self_w1[k * 32 + c]));
      acc0 = fmaf(x, wv.x, acc0);
      acc1 = fmaf(x, wv.y, acc1);
    }
    sdyn[i * 32 + c]     = acc0;
    sdyn[i * 32 + c + 1] = acc1;
  }
  __syncthreads();

  // ---- dyn = self_dyn + S@W2 + A*b2 + S ----
  for (int idx = t; idx < 512; idx += 256) {
    int i = idx >> 4, m = (idx & 15) * 2;
    float acc0 = sdyn[i * 32 + m]     + ssm[i * 32 + m]     + avec[i] * miscC[m];
    float acc1 = sdyn[i * 32 + m + 1] + ssm[i * 32 + m + 1] + avec[i] * miscC[m + 1];
    #pragma unroll
    for (int k = 0; k < 32; ++k) {
      float x = ssm[i * 32 + k];
      float2 wv = __ldg(reinterpret_cast<const float2*>(&p.rel_w2[k * 32 + m]));
      acc0 = fmaf(x, wv.x, acc0);
      acc1 = fmaf(x, wv.y, acc1);
    }
    sdyn[i * 32 + m]     = acc0;
    sdyn[i * 32 + m + 1] = acc1;
  }
  __syncthreads();

  // ---- tail MLP chain ----
  float* t1 = paF;
  float* t2 = paF + 1024;

  for (int idx = t; idx < 512; idx += 256) {
    int i = idx >> 4, c = (idx & 15) * 2;
    float2 b = __ldg(reinterpret_cast<const float2*>(&p.aff_b0[c]));
    float acc0 = b.x, acc1 = b.y;
    #pragma unroll
    for (int k = 0; k < 32; ++k) {
      float x = sdyn[i * 32 + k];
      float2 wv = __ldg(reinterpret_cast<const float2*>(&p.aff_w0[k * 32 + c]));
      acc0 = fmaf(x, wv.x, acc0);
      acc1 = fmaf(x, wv.y, acc1);
    }
    t1[i * 32 + c]     = tanhf(acc0);
    t1[i * 32 + c + 1] = tanhf(acc1);
  }
  __syncthreads();

  for (int idx = t; idx < 512; idx += 256) {
    int i = idx >> 4, c = (idx & 15) * 2;
    float2 b = __ldg(reinterpret_cast<const float2*>(&p.aff_b1[c]));
    float acc0 = b.x, acc1 = b.y;
    #pragma unroll
    for (int k = 0; k < 32; ++k) {
      float x = t1[i * 32 + k];
      float2 wv = __ldg(reinterpret_cast<const float2*>(&p.aff_w1[k * 32 + c]));
      acc0 = fmaf(x, wv.x, acc0);
      acc1 = fmaf(x, wv.y, acc1);
    }
    t2[i * 32 + c]     = tanhf(acc0) + t1[i * 32 + c];
    t2[i * 32 + c + 1] = tanhf(acc1) + t1[i * 32 + c + 1];
  }
  __syncthreads();

  for (int idx = t; idx < 512; idx += 256) {
    int i = idx >> 4, c = (idx & 15) * 2;
    float2 b = __ldg(reinterpret_cast<const float2*>(&p.aff_b2[c]));
    float acc0 = b.x, acc1 = b.y;
    #pragma unroll
    for (int k = 0; k < 32; ++k) {
      float x = t2[i * 32 + k];
      float2 wv = __ldg(reinterpret_cast<const float2*>(&p.aff_w2[k * 32 + c]));
      acc0 = fmaf(x, wv.x, acc0);
      acc1 = fmaf(x, wv.y, acc1);
    }
    t3s[i * 32 + c]     = acc0;
    t3s[i * 32 + c + 1] = acc1;
  }
  __syncthreads();

  for (int idx = t; idx < 512; idx += 256) {
    int i = idx >> 4, c = (idx & 15) * 2;
    float2 b = __ldg(reinterpret_cast<const float2*>(&p.out_b0[c]));
    float acc0 = b.x, acc1 = b.y;
    #pragma unroll
    for (int k = 0; k < 32; ++k) {
      float x = t3s[i * 32 + k];
      float2 wv = __ldg(reinterpret_cast<const float2*>(&p.out_w0[k * 32 + c]));
      acc0 = fmaf(x, wv.x, acc0);
      acc1 = fmaf(x, wv.y, acc1);
    }
    #pragma unroll
    for (int k = 0; k < 32; ++k) {
      float x = s2[i * 32 + k];
      float2 wv = __ldg(reinterpret_cast<const float2*>(&p.out_w0[(32 + k) * 32 + c]));
      acc0 = fmaf(x, wv.x, acc0);
      acc1 = fmaf(x, wv.y, acc1);
    }
    t1[i * 32 + c]     = tanhf(acc0);
    t1[i * 32 + c + 1] = tanhf(acc1);
  }
  __syncthreads();

  float* og = p.out + (size_t)n * (NOBJ * CL);
  for (int idx = t; idx < 512; idx += 256) {
    int i = idx >> 4, c = (idx & 15) * 2;
    float2 b = __ldg(reinterpret_cast<const float2*>(&p.out_b1[c]));
    float acc0 = b.x + t1[i * 32 + c];
    float acc1 = b.y + t1[i * 32 + c + 1];
    #pragma unroll
    for (int k = 0; k < 32; ++k) {
      float x = t1[i * 32 + k];
      float2 wv = __ldg(reinterpret_cast<const float2*>(&p.out_w1[k * 32 + c]));
      acc0 = fmaf(x, wv.x, acc0);
      acc1 = fmaf(x, wv.y, acc1);
    }
    og[i * 32 + c]     = acc0;
    og[i * 32 + c + 1] = acc1;
  }
}

extern "C" void kernel_launch(void* const* d_in, const int* in_sizes, int n_in,
                              void* d_out, int out_size)
{
  Params p;
  p.s       = (const float*)d_in[0];
  p.enc_w   = (const float*)d_in[1];  p.enc_b   = (const float*)d_in[2];
  p.self_w0 = (const float*)d_in[3];  p.self_b0 = (const float*)d_in[4];
  p.self_w1 = (const float*)d_in[5];  p.self_b1 = (const float*)d_in[6];
  p.rel_w0  = (const float*)d_in[7];  p.rel_b0  = (const float*)d_in[8];
  p.rel_w1  = (const float*)d_in[9];  p.rel_b1  = (const float*)d_in[10];
  p.rel_w2  = (const float*)d_in[11]; p.rel_b2  = (const float*)d_in[12];
  p.att_w0  = (const float*)d_in[13]; p.att_b0  = (const float*)d_in[14];
  p.att_w1  = (const float*)d_in[15]; p.att_b1  = (const float*)d_in[16];
  p.att_w2  = (const float*)d_in[17]; p.att_b2  = (const float*)d_in[18];
  p.aff_w0  = (const float*)d_in[19]; p.aff_b0  = (const float*)d_in[20];
  p.aff_w1  = (const float*)d_in[21]; p.aff_b1  = (const float*)d_in[22];
  p.aff_w2  = (const float*)d_in[23]; p.aff_b2  = (const float*)d_in[24];
  p.out_w0  = (const float*)d_in[25]; p.out_b0  = (const float*)d_in[26];
  p.out_w1  = (const float*)d_in[27]; p.out_b1  = (const float*)d_in[28];
  p.out     = (float*)d_out;

  int N = in_sizes[0] / (NOBJ * (CL / 2));
  dynamics_kernel<<<N, 256>>>(p);
}